// round 2
// baseline (speedup 1.0000x reference)
#include <cuda_runtime.h>
#include <cooperative_groups.h>
namespace cg = cooperative_groups;

// ------------------------- scratch (device globals) -------------------------
#define BT (256*512)
__device__ float g_x64 [256*64];
__device__ float g_xg1f[(size_t)BT*512];
__device__ float g_xg1b[(size_t)BT*512];
__device__ float g_Y   [(size_t)BT*256];
__device__ float g_xg2f[(size_t)BT*256];
__device__ float g_xg2b[(size_t)BT*256];
__device__ float g_h2  [256*128];

// ------------------------- embedding MLP branch -----------------------------
__global__ void __launch_bounds__(256)
emb_mlp_kernel(const int* __restrict__ inputA, const float* __restrict__ emb,
               const float* __restrict__ w1, const float* __restrict__ b1,
               const float* __restrict__ w2, const float* __restrict__ b2,
               const float* __restrict__ w3, const float* __restrict__ b3,
               float* __restrict__ xout)
{
    __shared__ float x0[600], x1[256], x2[128];
    const int b = blockIdx.x, tid = threadIdx.x;
    for (int i = tid; i < 600; i += 256) {
        int la = i / 3, comp = i - la * 3;
        x0[i] = emb[inputA[b*200 + la]*3 + comp];
    }
    __syncthreads();
    {
        float acc = b1[tid];
        #pragma unroll 4
        for (int k = 0; k < 600; ++k) acc += x0[k] * w1[k*256 + tid];
        x1[tid] = fmaxf(acc, 0.f);
    }
    __syncthreads();
    if (tid < 128) {
        float acc = b2[tid];
        #pragma unroll 4
        for (int k = 0; k < 256; ++k) acc += x1[k] * w2[k*128 + tid];
        x2[tid] = fmaxf(acc, 0.f);
    }
    __syncthreads();
    if (tid < 64) {
        float acc = b3[tid];
        #pragma unroll 4
        for (int k = 0; k < 128; ++k) acc += x2[k] * w3[k*64 + tid];
        xout[b*64 + tid] = fmaxf(acc, 0.f);
    }
}

// ------------- SGEMM + bias: C[M,N] = A[M,K] @ W[K,N] + bias ---------------
// BM=BN=128, BK=16, 256 threads, 8x8 microtile. M%128==0, N%128==0, K%16==0.
__global__ void __launch_bounds__(256)
gemm_bias_kernel(const float* __restrict__ A, const float* __restrict__ W,
                 const float* __restrict__ bias, float* __restrict__ C,
                 int M, int N, int K)
{
    __shared__ float As[16][128];
    __shared__ float Bs[16][128];
    const int tid = threadIdx.x;
    const int m0 = blockIdx.x * 128, n0 = blockIdx.y * 128;
    const int tx = tid & 15, ty = tid >> 4;

    float acc[8][8];
    #pragma unroll
    for (int i = 0; i < 8; ++i)
        #pragma unroll
        for (int j = 0; j < 8; ++j) acc[i][j] = 0.f;

    const int ar = tid >> 2, ac = (tid & 3) << 2;
    const int bkr = tid >> 5, bnc = (tid & 31) << 2;

    for (int k0 = 0; k0 < K; k0 += 16) {
        #pragma unroll
        for (int h = 0; h < 2; ++h) {
            float4 av = *(const float4*)(A + (size_t)(m0 + ar + h*64) * K + k0 + ac);
            As[ac+0][ar+h*64] = av.x; As[ac+1][ar+h*64] = av.y;
            As[ac+2][ar+h*64] = av.z; As[ac+3][ar+h*64] = av.w;
        }
        #pragma unroll
        for (int h = 0; h < 2; ++h)
            *(float4*)&Bs[bkr + h*8][bnc] =
                *(const float4*)(W + (size_t)(k0 + bkr + h*8) * N + n0 + bnc);
        __syncthreads();
        #pragma unroll
        for (int k = 0; k < 16; ++k) {
            float a_[8], b_[8];
            #pragma unroll
            for (int i = 0; i < 8; ++i) a_[i] = As[k][ty*8 + i];
            #pragma unroll
            for (int j = 0; j < 8; ++j) b_[j] = Bs[k][tx + 16*j];
            #pragma unroll
            for (int i = 0; i < 8; ++i)
                #pragma unroll
                for (int j = 0; j < 8; ++j) acc[i][j] += a_[i] * b_[j];
        }
        __syncthreads();
    }
    float bj[8];
    #pragma unroll
    for (int j = 0; j < 8; ++j) bj[j] = bias[n0 + tx + 16*j];
    #pragma unroll
    for (int i = 0; i < 8; ++i) {
        size_t row = (size_t)(m0 + ty*8 + i) * N;
        #pragma unroll
        for (int j = 0; j < 8; ++j) C[row + n0 + tx + 16*j] = acc[i][j] + bj[j];
    }
}

// -------------------- LSTM layer 1 (H=128), 2-CTA cluster -------------------
// grid (64, 2): x = 32 batch tiles * 2 ranks (cluster pairs), y = direction.
// Each rank owns h-indices [rank*64, rank*64+64) -> 256 of 512 gate columns.
// SMEM: ws[256][132] transposed Wr slice; hbuf[2][8][128]; gbuf[8][256]; c[8][64]
__global__ void __cluster_dims__(2,1,1) __launch_bounds__(256, 1)
lstm1_kernel(const float* __restrict__ xg1f, const float* __restrict__ xg1b,
             const float* __restrict__ r1f,  const float* __restrict__ r1b,
             float* __restrict__ Y)
{
    extern __shared__ float sm[];
    float* ws   = sm;                    // 256*132
    float* hbuf = sm + 256*132;          // 2*8*128
    float* gbuf = hbuf + 2*8*128;        // 8*256
    float* cst  = gbuf + 8*256;          // 8*64

    cg::cluster_group cl = cg::this_cluster();
    const int rank = cl.block_rank();
    const int dir  = blockIdx.y;
    const int b0   = (blockIdx.x >> 1) * 8;
    const int tid  = threadIdx.x;
    const float* xg = dir ? xg1b : xg1f;
    const float* Wr = dir ? r1b : r1f;

    for (int it = 0; it < 128; ++it) {
        int idx = tid + it*256;
        int c = idx & 255, k = idx >> 8;
        int gcol = ((c >> 6) << 7) + (rank << 6) + (c & 63);
        ws[c*132 + k] = Wr[k*512 + gcol];
    }
    for (int i = tid; i < 8*128; i += 256) hbuf[i] = 0.f;
    for (int i = tid; i < 8*64;  i += 256) cst[i]  = 0.f;

    float* peer_h = cl.map_shared_rank(hbuf, rank ^ 1);
    cl.sync();

    const int bg = tid >> 7;             // batch half: rows bg*4..bg*4+3
    const int cp = tid & 127;            // owns local cols cp and cp+128
    const bool relu1 = (cp < 64);        // col cp+128 is gate 2 (relu) if cp<64
    const int j  = cp & 63;
    const int gc0 = ((cp >> 6) << 7) + (rank << 6) + j;          // gate 0/1
    const int gc1 = (((cp >> 6) + 2) << 7) + (rank << 6) + j;    // gate 2/3
    const float4* w0p = (const float4*)(ws + cp*132);
    const float4* w1p = (const float4*)(ws + (cp + 128)*132);

    for (int t = 0; t < 512; ++t) {
        const int tt  = dir ? (511 - t) : t;
        const int cur = t & 1, nxt = cur ^ 1;

        float xv0[4], xv1[4];
        #pragma unroll
        for (int i = 0; i < 4; ++i) {
            size_t base = ((size_t)(b0 + (bg<<2) + i) * 512 + tt) * 512;
            xv0[i] = xg[base + gc0];
            xv1[i] = xg[base + gc1];
        }

        float a0[4] = {0.f,0.f,0.f,0.f}, a1[4] = {0.f,0.f,0.f,0.f};
        const float4* hp = (const float4*)(hbuf + cur*1024 + (bg<<2)*128);
        #pragma unroll 4
        for (int q = 0; q < 32; ++q) {
            float4 w0 = w0p[q], w1 = w1p[q];
            #pragma unroll
            for (int i = 0; i < 4; ++i) {
                float4 h4 = hp[i*32 + q];
                a0[i] += h4.x*w0.x + h4.y*w0.y + h4.z*w0.z + h4.w*w0.w;
                a1[i] += h4.x*w1.x + h4.y*w1.y + h4.z*w1.z + h4.w*w1.w;
            }
        }
        #pragma unroll
        for (int i = 0; i < 4; ++i) {
            float g0 = a0[i] + xv0[i];
            float g1 = a1[i] + xv1[i];
            g0 = 1.f / (1.f + __expf(-g0));
            g1 = relu1 ? fmaxf(g1, 0.f) : 1.f / (1.f + __expf(-g1));
            int bb = (bg << 2) + i;
            gbuf[bb*256 + cp]       = g0;
            gbuf[bb*256 + 128 + cp] = g1;
        }
        __syncthreads();

        #pragma unroll
        for (int s = tid; s < 512; s += 256) {
            int b = s >> 6, jj = s & 63;
            float iv = gbuf[b*256 + jj];
            float fv = gbuf[b*256 + 64 + jj];
            float cc = gbuf[b*256 + 128 + jj];
            float ov = gbuf[b*256 + 192 + jj];
            float cv = fv * cst[s] + iv * cc;
            cst[s] = cv;
            float hv = ov * fmaxf(cv, 0.f);
            int jg = (rank << 6) + jj;
            hbuf[nxt*1024 + b*128 + jg]  = hv;
            peer_h[nxt*1024 + b*128 + jg] = hv;
            Y[((size_t)(b0 + b) * 512 + tt) * 256 + dir*128 + jg] = hv;
        }
        cl.sync();
    }
}

// ------------------------- LSTM layer 2 (H=64) ------------------------------
// grid (64, 2): batch tile of 4, dir. 256 threads = 256 gate cols.
__global__ void __launch_bounds__(256, 1)
lstm2_kernel(const float* __restrict__ xg2f, const float* __restrict__ xg2b,
             const float* __restrict__ r2f,  const float* __restrict__ r2b,
             float* __restrict__ hout)
{
    extern __shared__ float sm[];
    float* ws   = sm;                // 256*68
    float* hbuf = sm + 256*68;       // 2*4*64
    float* gbuf = hbuf + 2*4*64;     // 4*256
    float* cst  = gbuf + 4*256;      // 4*64

    const int dir = blockIdx.y;
    const int b0  = blockIdx.x * 4;
    const int tid = threadIdx.x;
    const float* xg = dir ? xg2b : xg2f;
    const float* Wr = dir ? r2b : r2f;

    for (int it = 0; it < 64; ++it) {
        int idx = tid + it*256;
        int c = idx & 255, k = idx >> 8;
        ws[c*68 + k] = Wr[k*256 + c];
    }
    for (int i = tid; i < 4*64*2; i += 256) hbuf[i] = 0.f;
    if (tid < 256) cst[tid & 255] = 0.f;
    __syncthreads();

    const int c = tid;
    const int gate = c >> 6;
    const float4* wp = (const float4*)(ws + c*68);

    for (int t = 0; t < 512; ++t) {
        const int tt  = dir ? (511 - t) : t;
        const int cur = t & 1, nxt = cur ^ 1;

        float xv[4];
        #pragma unroll
        for (int i = 0; i < 4; ++i)
            xv[i] = xg[((size_t)(b0 + i) * 512 + tt) * 256 + c];

        float a[4] = {0.f,0.f,0.f,0.f};
        const float4* hp = (const float4*)(hbuf + cur*256);
        #pragma unroll 4
        for (int q = 0; q < 16; ++q) {
            float4 w4 = wp[q];
            #pragma unroll
            for (int i = 0; i < 4; ++i) {
                float4 h4 = hp[i*16 + q];
                a[i] += h4.x*w4.x + h4.y*w4.y + h4.z*w4.z + h4.w*w4.w;
            }
        }
        #pragma unroll
        for (int i = 0; i < 4; ++i) {
            float g = a[i] + xv[i];
            g = (gate == 2) ? fmaxf(g, 0.f) : 1.f / (1.f + __expf(-g));
            gbuf[i*256 + c] = g;
        }
        __syncthreads();

        {
            int b = tid >> 6, jj = tid & 63;
            float iv = gbuf[b*256 + jj];
            float fv = gbuf[b*256 + 64 + jj];
            float cc = gbuf[b*256 + 128 + jj];
            float ov = gbuf[b*256 + 192 + jj];
            float cv = fv * cst[tid] + iv * cc;
            cst[tid] = cv;
            hbuf[nxt*256 + b*64 + jj] = ov * fmaxf(cv, 0.f);
        }
        __syncthreads();
    }
    {
        int b = tid >> 6, jj = tid & 63;
        hout[(size_t)(b0 + b) * 128 + dir*64 + jj] = hbuf[0*256 + b*64 + jj];
    }
}

// ------------------------------ heads ---------------------------------------
__global__ void __launch_bounds__(256)
head_kernel(const float* __restrict__ x64, const float* __restrict__ h2,
            const float* __restrict__ wz1, const float* __restrict__ bz1,
            const float* __restrict__ wz2, const float* __restrict__ bz2,
            const float* __restrict__ wt1, const float* __restrict__ bt1,
            const float* __restrict__ wt2, const float* __restrict__ bt2,
            float* __restrict__ out)
{
    const int b = threadIdx.x;
    float comb[192];
    #pragma unroll 4
    for (int k = 0; k < 64; ++k)  comb[k]      = x64[b*64 + k];
    #pragma unroll 4
    for (int k = 0; k < 128; ++k) comb[64 + k] = h2[b*128 + k];

    float z0 = bz1[0], z1 = bz1[1], t0 = bt1[0], t1 = bt1[1];
    #pragma unroll 4
    for (int k = 0; k < 192; ++k) {
        float v = comb[k];
        z0 += v * wz1[k*2 + 0]; z1 += v * wz1[k*2 + 1];
        t0 += v * wt1[k*2 + 0]; t1 += v * wt1[k*2 + 1];
    }
    out[b]       = fmaxf(z0,0.f)*wz2[0] + fmaxf(z1,0.f)*wz2[1] + bz2[0];
    out[256 + b] = fmaxf(t0,0.f)*wt2[0] + fmaxf(t1,0.f)*wt2[1] + bt2[0];
}

// ------------------------------ launcher ------------------------------------
extern "C" void kernel_launch(void* const* d_in, const int* in_sizes, int n_in,
                              void* d_out, int out_size)
{
    const int*   inputA = (const int*)  d_in[0];
    const float* inputB = (const float*)d_in[1];
    const float* emb = (const float*)d_in[2];
    const float *w1=(const float*)d_in[3],  *b1=(const float*)d_in[4];
    const float *w2=(const float*)d_in[5],  *b2=(const float*)d_in[6];
    const float *w3=(const float*)d_in[7],  *b3=(const float*)d_in[8];
    const float *k1f=(const float*)d_in[9],  *r1f=(const float*)d_in[10], *bb1f=(const float*)d_in[11];
    const float *k1b=(const float*)d_in[12], *r1b=(const float*)d_in[13], *bb1b=(const float*)d_in[14];
    const float *k2f=(const float*)d_in[15], *r2f=(const float*)d_in[16], *bb2f=(const float*)d_in[17];
    const float *k2b=(const float*)d_in[18], *r2b=(const float*)d_in[19], *bb2b=(const float*)d_in[20];
    const float *wz1=(const float*)d_in[21], *bz1=(const float*)d_in[22];
    const float *wz2=(const float*)d_in[23], *bz2=(const float*)d_in[24];
    const float *wt1=(const float*)d_in[25], *bt1=(const float*)d_in[26];
    const float *wt2=(const float*)d_in[27], *bt2=(const float*)d_in[28];
    float* out = (float*)d_out;

    float *xg1f, *xg1b, *Y, *xg2f, *xg2b, *x64, *h2;
    cudaGetSymbolAddress((void**)&xg1f, g_xg1f);
    cudaGetSymbolAddress((void**)&xg1b, g_xg1b);
    cudaGetSymbolAddress((void**)&Y,    g_Y);
    cudaGetSymbolAddress((void**)&xg2f, g_xg2f);
    cudaGetSymbolAddress((void**)&xg2b, g_xg2b);
    cudaGetSymbolAddress((void**)&x64,  g_x64);
    cudaGetSymbolAddress((void**)&h2,   g_h2);

    static bool attr_done = false;
    if (!attr_done) {
        cudaFuncSetAttribute(lstm1_kernel, cudaFuncAttributeMaxDynamicSharedMemorySize, 160*1024);
        cudaFuncSetAttribute(lstm2_kernel, cudaFuncAttributeMaxDynamicSharedMemorySize, 80*1024);
        attr_done = true;
    }

    emb_mlp_kernel<<<256, 256>>>(inputA, emb, w1,b1, w2,b2, w3,b3, x64);

    gemm_bias_kernel<<<dim3(1024,4), 256>>>(inputB, k1f, bb1f, xg1f, BT, 512, 128);
    gemm_bias_kernel<<<dim3(1024,4), 256>>>(inputB, k1b, bb1b, xg1b, BT, 512, 128);

    size_t sm1 = (256*132 + 2*8*128 + 8*256 + 8*64) * sizeof(float);
    lstm1_kernel<<<dim3(64,2), 256, sm1>>>(xg1f, xg1b, r1f, r1b, Y);

    gemm_bias_kernel<<<dim3(1024,2), 256>>>(Y, k2f, bb2f, xg2f, BT, 256, 256);
    gemm_bias_kernel<<<dim3(1024,2), 256>>>(Y, k2b, bb2b, xg2b, BT, 256, 256);

    size_t sm2 = (256*68 + 2*4*64 + 4*256 + 4*64) * sizeof(float);
    lstm2_kernel<<<dim3(64,2), 256, sm2>>>(xg2f, xg2b, r2f, r2b, h2);

    head_kernel<<<1, 256>>>(x64, h2, wz1,bz1, wz2,bz2, wt1,bt1, wt2,bt2, out);
}

// round 4
// speedup vs baseline: 1.3418x; 1.3418x over previous
#include <cuda_runtime.h>
#include <cooperative_groups.h>
#include <cstdint>
namespace cg = cooperative_groups;

// ------------------------- scratch (device globals) -------------------------
#define BT (256*512)
__device__ float g_x64 [256*64];
__device__ float g_xg1f[(size_t)BT*512];
__device__ float g_xg1b[(size_t)BT*512];
__device__ float g_Y   [(size_t)BT*256];
__device__ float g_xg2f[(size_t)BT*256];
__device__ float g_xg2b[(size_t)BT*256];
__device__ float g_h2  [256*128];

// ------------------------- small PTX helpers --------------------------------
__device__ __forceinline__ uint32_t smem_u32(const void* p) {
    uint32_t a;
    asm("{ .reg .u64 t; cvta.to.shared.u64 t, %1; cvt.u32.u64 %0, t; }" : "=r"(a) : "l"(p));
    return a;
}
__device__ __forceinline__ uint32_t f2tf32(float v) {
    uint32_t r;
    asm("cvt.rna.tf32.f32 %0, %1;" : "=r"(r) : "f"(v));
    return r;
}
__device__ __forceinline__ void mma_tf32(float* c, const uint32_t* a, const uint32_t* b) {
    asm volatile("mma.sync.aligned.m16n8k8.row.col.f32.tf32.tf32.f32 "
        "{%0,%1,%2,%3},{%4,%5,%6,%7},{%8,%9},{%0,%1,%2,%3};"
        : "+f"(c[0]), "+f"(c[1]), "+f"(c[2]), "+f"(c[3])
        : "r"(a[0]), "r"(a[1]), "r"(a[2]), "r"(a[3]), "r"(b[0]), "r"(b[1]));
}
#define CP_ASYNC16(dst, src) asm volatile("cp.async.cg.shared.global [%0], [%1], 16;" :: "r"(dst), "l"(src))
#define CP_COMMIT()          asm volatile("cp.async.commit_group;" ::: "memory")
#define CP_WAIT(n)           asm volatile("cp.async.wait_group %0;" :: "n"(n) : "memory")

// ------------- tf32 mma.sync GEMM + bias: C[M,N]=A[M,K]@W[K,N]+b -----------
// Block 128x128, BK=32, 2-stage cp.async pipeline, 8 warps (2m x 4n),
// warp tile 64x32, m16n8k8 fragments. M%128==0, N%128==0, K%32==0.
// SMEM per stage: A [128][36] f32 (18432B) + B [32][132] f32 (16896B).
#define STAGE_BYTES 35328
__global__ void __launch_bounds__(256, 2)
gemm_mma_kernel(const float* __restrict__ A, const float* __restrict__ W,
                const float* __restrict__ bias, float* __restrict__ C,
                int M, int N, int K)
{
    extern __shared__ char smem[];
    const uint32_t smem_base = smem_u32(smem);
    const int tid = threadIdx.x;
    const int lane = tid & 31, wid = tid >> 5;
    const int m0 = blockIdx.x * 128, n0 = blockIdx.y * 128;
    const int wm = (wid >> 2) * 64, wn = (wid & 3) * 32;

    float acc[4][4][4];
    #pragma unroll
    for (int mt = 0; mt < 4; ++mt)
        #pragma unroll
        for (int nt = 0; nt < 4; ++nt)
            #pragma unroll
            for (int q = 0; q < 4; ++q) acc[mt][nt][q] = 0.f;

    const int nch = K >> 5;

    // --- async copy of one K-chunk into a stage ---
    auto issue = [&](int ch, int stage) {
        const int kc = ch << 5;
        const uint32_t sA = smem_base + stage * STAGE_BYTES;
        const uint32_t sB = sA + 18432u;
        #pragma unroll
        for (int i = 0; i < 4; ++i) {          // A: 128 rows x 8 float4
            int idx = tid + i * 256;
            int row = idx >> 3, c4 = idx & 7;
            CP_ASYNC16(sA + row * 144 + c4 * 16,
                       A + (size_t)(m0 + row) * K + kc + c4 * 4);
        }
        #pragma unroll
        for (int i = 0; i < 4; ++i) {          // B: 32 k-rows x 32 float4
            int idx = tid + i * 256;
            int kr = idx >> 5, c4 = idx & 31;
            CP_ASYNC16(sB + kr * 528 + c4 * 16,
                       W + (size_t)(kc + kr) * N + n0 + c4 * 4);
        }
        CP_COMMIT();
    };

    issue(0, 0);
    for (int ch = 0; ch < nch; ++ch) {
        if (ch + 1 < nch) { issue(ch + 1, (ch + 1) & 1); CP_WAIT(1); }
        else             { CP_WAIT(0); }
        __syncthreads();

        const float* As = (const float*)(smem + (ch & 1) * STAGE_BYTES);
        const float* Bs = As + 4608;           // 18432/4

        #pragma unroll
        for (int k8 = 0; k8 < 4; ++k8) {
            const int kk = k8 * 8;
            uint32_t a[4][4], b[4][2];
            #pragma unroll
            for (int mt = 0; mt < 4; ++mt) {
                int r = wm + mt * 16 + (lane >> 2);
                a[mt][0] = f2tf32(As[r * 36 + kk + (lane & 3)]);
                a[mt][1] = f2tf32(As[(r + 8) * 36 + kk + (lane & 3)]);
                a[mt][2] = f2tf32(As[r * 36 + kk + 4 + (lane & 3)]);
                a[mt][3] = f2tf32(As[(r + 8) * 36 + kk + 4 + (lane & 3)]);
            }
            #pragma unroll
            for (int nt = 0; nt < 4; ++nt) {
                int n = wn + nt * 8 + (lane >> 2);
                b[nt][0] = f2tf32(Bs[(kk + (lane & 3)) * 132 + n]);
                b[nt][1] = f2tf32(Bs[(kk + 4 + (lane & 3)) * 132 + n]);
            }
            #pragma unroll
            for (int mt = 0; mt < 4; ++mt)
                #pragma unroll
                for (int nt = 0; nt < 4; ++nt)
                    mma_tf32(acc[mt][nt], a[mt], b[nt]);
        }
        __syncthreads();
    }

    // --- epilogue: add bias, store ---
    #pragma unroll
    for (int mt = 0; mt < 4; ++mt) {
        int r = m0 + wm + mt * 16 + (lane >> 2);
        #pragma unroll
        for (int nt = 0; nt < 4; ++nt) {
            int col = n0 + wn + nt * 8 + (lane & 3) * 2;
            float b0 = __ldg(bias + col), b1 = __ldg(bias + col + 1);
            float2 v0 = make_float2(acc[mt][nt][0] + b0, acc[mt][nt][1] + b1);
            float2 v1 = make_float2(acc[mt][nt][2] + b0, acc[mt][nt][3] + b1);
            *(float2*)(C + (size_t)r * N + col)       = v0;
            *(float2*)(C + (size_t)(r + 8) * N + col) = v1;
        }
    }
}

// ------------------------- embedding MLP branch -----------------------------
__global__ void __launch_bounds__(256)
emb_mlp_kernel(const int* __restrict__ inputA, const float* __restrict__ emb,
               const float* __restrict__ w1, const float* __restrict__ b1,
               const float* __restrict__ w2, const float* __restrict__ b2,
               const float* __restrict__ w3, const float* __restrict__ b3,
               float* __restrict__ xout)
{
    __shared__ float x0[600], x1[256], x2[128];
    const int b = blockIdx.x, tid = threadIdx.x;
    for (int i = tid; i < 600; i += 256) {
        int la = i / 3, comp = i - la * 3;
        x0[i] = emb[inputA[b*200 + la]*3 + comp];
    }
    __syncthreads();
    {
        float acc = b1[tid];
        #pragma unroll 4
        for (int k = 0; k < 600; ++k) acc += x0[k] * w1[k*256 + tid];
        x1[tid] = fmaxf(acc, 0.f);
    }
    __syncthreads();
    if (tid < 128) {
        float acc = b2[tid];
        #pragma unroll 4
        for (int k = 0; k < 256; ++k) acc += x1[k] * w2[k*128 + tid];
        x2[tid] = fmaxf(acc, 0.f);
    }
    __syncthreads();
    if (tid < 64) {
        float acc = b3[tid];
        #pragma unroll 4
        for (int k = 0; k < 128; ++k) acc += x2[k] * w3[k*64 + tid];
        xout[b*64 + tid] = fmaxf(acc, 0.f);
    }
}

// -------------------- LSTM layer 1 (H=128), 2-CTA cluster -------------------
__global__ void __cluster_dims__(2,1,1) __launch_bounds__(256, 1)
lstm1_kernel(const float* __restrict__ xg1f, const float* __restrict__ xg1b,
             const float* __restrict__ r1f,  const float* __restrict__ r1b,
             float* __restrict__ Y)
{
    extern __shared__ float sm[];
    float* ws   = sm;                    // 256*132
    float* hbuf = sm + 256*132;          // 2*8*128
    float* gbuf = hbuf + 2*8*128;        // 8*256
    float* cst  = gbuf + 8*256;          // 8*64

    cg::cluster_group cl = cg::this_cluster();
    const int rank = cl.block_rank();
    const int dir  = blockIdx.y;
    const int b0   = (blockIdx.x >> 1) * 8;
    const int tid  = threadIdx.x;
    const float* xg = dir ? xg1b : xg1f;
    const float* Wr = dir ? r1b : r1f;

    for (int it = 0; it < 128; ++it) {
        int idx = tid + it*256;
        int c = idx & 255, k = idx >> 8;
        int gcol = ((c >> 6) << 7) + (rank << 6) + (c & 63);
        ws[c*132 + k] = Wr[k*512 + gcol];
    }
    for (int i = tid; i < 8*128; i += 256) hbuf[i] = 0.f;
    for (int i = tid; i < 8*64;  i += 256) cst[i]  = 0.f;

    float* peer_h = cl.map_shared_rank(hbuf, rank ^ 1);
    cl.sync();

    const int bg = tid >> 7;
    const int cp = tid & 127;
    const bool relu1 = (cp < 64);
    const int j  = cp & 63;
    const int gc0 = ((cp >> 6) << 7) + (rank << 6) + j;
    const int gc1 = (((cp >> 6) + 2) << 7) + (rank << 6) + j;
    const float4* w0p = (const float4*)(ws + cp*132);
    const float4* w1p = (const float4*)(ws + (cp + 128)*132);

    for (int t = 0; t < 512; ++t) {
        const int tt  = dir ? (511 - t) : t;
        const int cur = t & 1, nxt = cur ^ 1;

        float xv0[4], xv1[4];
        #pragma unroll
        for (int i = 0; i < 4; ++i) {
            size_t base = ((size_t)(b0 + (bg<<2) + i) * 512 + tt) * 512;
            xv0[i] = xg[base + gc0];
            xv1[i] = xg[base + gc1];
        }

        float a0[4] = {0.f,0.f,0.f,0.f}, a1[4] = {0.f,0.f,0.f,0.f};
        const float4* hp = (const float4*)(hbuf + cur*1024 + (bg<<2)*128);
        #pragma unroll 4
        for (int q = 0; q < 32; ++q) {
            float4 w0 = w0p[q], w1 = w1p[q];
            #pragma unroll
            for (int i = 0; i < 4; ++i) {
                float4 h4 = hp[i*32 + q];
                a0[i] += h4.x*w0.x + h4.y*w0.y + h4.z*w0.z + h4.w*w0.w;
                a1[i] += h4.x*w1.x + h4.y*w1.y + h4.z*w1.z + h4.w*w1.w;
            }
        }
        #pragma unroll
        for (int i = 0; i < 4; ++i) {
            float g0 = a0[i] + xv0[i];
            float g1 = a1[i] + xv1[i];
            g0 = 1.f / (1.f + __expf(-g0));
            g1 = relu1 ? fmaxf(g1, 0.f) : 1.f / (1.f + __expf(-g1));
            int bb = (bg << 2) + i;
            gbuf[bb*256 + cp]       = g0;
            gbuf[bb*256 + 128 + cp] = g1;
        }
        __syncthreads();

        #pragma unroll
        for (int s = tid; s < 512; s += 256) {
            int b = s >> 6, jj = s & 63;
            float iv = gbuf[b*256 + jj];
            float fv = gbuf[b*256 + 64 + jj];
            float cc = gbuf[b*256 + 128 + jj];
            float ov = gbuf[b*256 + 192 + jj];
            float cv = fv * cst[s] + iv * cc;
            cst[s] = cv;
            float hv = ov * fmaxf(cv, 0.f);
            int jg = (rank << 6) + jj;
            hbuf[nxt*1024 + b*128 + jg]  = hv;
            peer_h[nxt*1024 + b*128 + jg] = hv;
            Y[((size_t)(b0 + b) * 512 + tt) * 256 + dir*128 + jg] = hv;
        }
        cl.sync();
    }
}

// ------------------------- LSTM layer 2 (H=64) ------------------------------
__global__ void __launch_bounds__(256, 1)
lstm2_kernel(const float* __restrict__ xg2f, const float* __restrict__ xg2b,
             const float* __restrict__ r2f,  const float* __restrict__ r2b,
             float* __restrict__ hout)
{
    extern __shared__ float sm[];
    float* ws   = sm;                // 256*68
    float* hbuf = sm + 256*68;       // 2*4*64
    float* gbuf = hbuf + 2*4*64;     // 4*256
    float* cst  = gbuf + 4*256;      // 4*64

    const int dir = blockIdx.y;
    const int b0  = blockIdx.x * 4;
    const int tid = threadIdx.x;
    const float* xg = dir ? xg2b : xg2f;
    const float* Wr = dir ? r2b : r2f;

    for (int it = 0; it < 64; ++it) {
        int idx = tid + it*256;
        int c = idx & 255, k = idx >> 8;
        ws[c*68 + k] = Wr[k*256 + c];
    }
    for (int i = tid; i < 4*64*2; i += 256) hbuf[i] = 0.f;
    cst[tid] = 0.f;
    __syncthreads();

    const int c = tid;
    const int gate = c >> 6;
    const float4* wp = (const float4*)(ws + c*68);

    for (int t = 0; t < 512; ++t) {
        const int tt  = dir ? (511 - t) : t;
        const int cur = t & 1, nxt = cur ^ 1;

        float xv[4];
        #pragma unroll
        for (int i = 0; i < 4; ++i)
            xv[i] = xg[((size_t)(b0 + i) * 512 + tt) * 256 + c];

        float a[4] = {0.f,0.f,0.f,0.f};
        const float4* hp = (const float4*)(hbuf + cur*256);
        #pragma unroll 4
        for (int q = 0; q < 16; ++q) {
            float4 w4 = wp[q];
            #pragma unroll
            for (int i = 0; i < 4; ++i) {
                float4 h4 = hp[i*16 + q];
                a[i] += h4.x*w4.x + h4.y*w4.y + h4.z*w4.z + h4.w*w4.w;
            }
        }
        #pragma unroll
        for (int i = 0; i < 4; ++i) {
            float g = a[i] + xv[i];
            g = (gate == 2) ? fmaxf(g, 0.f) : 1.f / (1.f + __expf(-g));
            gbuf[i*256 + c] = g;
        }
        __syncthreads();

        {
            int b = tid >> 6, jj = tid & 63;
            float iv = gbuf[b*256 + jj];
            float fv = gbuf[b*256 + 64 + jj];
            float cc = gbuf[b*256 + 128 + jj];
            float ov = gbuf[b*256 + 192 + jj];
            float cv = fv * cst[tid] + iv * cc;
            cst[tid] = cv;
            hbuf[nxt*256 + b*64 + jj] = ov * fmaxf(cv, 0.f);
        }
        __syncthreads();
    }
    {
        int b = tid >> 6, jj = tid & 63;
        hout[(size_t)(b0 + b) * 128 + dir*64 + jj] = hbuf[0*256 + b*64 + jj];
    }
}

// ------------------------------ heads ---------------------------------------
__global__ void __launch_bounds__(256)
head_kernel(const float* __restrict__ x64, const float* __restrict__ h2,
            const float* __restrict__ wz1, const float* __restrict__ bz1,
            const float* __restrict__ wz2, const float* __restrict__ bz2,
            const float* __restrict__ wt1, const float* __restrict__ bt1,
            const float* __restrict__ wt2, const float* __restrict__ bt2,
            float* __restrict__ out)
{
    const int b = threadIdx.x;
    float comb[192];
    #pragma unroll 4
    for (int k = 0; k < 64; ++k)  comb[k]      = x64[b*64 + k];
    #pragma unroll 4
    for (int k = 0; k < 128; ++k) comb[64 + k] = h2[b*128 + k];

    float z0 = bz1[0], z1 = bz1[1], t0 = bt1[0], t1 = bt1[1];
    #pragma unroll 4
    for (int k = 0; k < 192; ++k) {
        float v = comb[k];
        z0 += v * wz1[k*2 + 0]; z1 += v * wz1[k*2 + 1];
        t0 += v * wt1[k*2 + 0]; t1 += v * wt1[k*2 + 1];
    }
    out[b]       = fmaxf(z0,0.f)*wz2[0] + fmaxf(z1,0.f)*wz2[1] + bz2[0];
    out[256 + b] = fmaxf(t0,0.f)*wt2[0] + fmaxf(t1,0.f)*wt2[1] + bt2[0];
}

// ------------------------------ launcher ------------------------------------
extern "C" void kernel_launch(void* const* d_in, const int* in_sizes, int n_in,
                              void* d_out, int out_size)
{
    const int*   inputA = (const int*)  d_in[0];
    const float* inputB = (const float*)d_in[1];
    const float* emb = (const float*)d_in[2];
    const float *w1=(const float*)d_in[3],  *b1=(const float*)d_in[4];
    const float *w2=(const float*)d_in[5],  *b2=(const float*)d_in[6];
    const float *w3=(const float*)d_in[7],  *b3=(const float*)d_in[8];
    const float *k1f=(const float*)d_in[9],  *r1f=(const float*)d_in[10], *bb1f=(const float*)d_in[11];
    const float *k1b=(const float*)d_in[12], *r1b=(const float*)d_in[13], *bb1b=(const float*)d_in[14];
    const float *k2f=(const float*)d_in[15], *r2f=(const float*)d_in[16], *bb2f=(const float*)d_in[17];
    const float *k2b=(const float*)d_in[18], *r2b=(const float*)d_in[19], *bb2b=(const float*)d_in[20];
    const float *wz1=(const float*)d_in[21], *bz1=(const float*)d_in[22];
    const float *wz2=(const float*)d_in[23], *bz2=(const float*)d_in[24];
    const float *wt1=(const float*)d_in[25], *bt1=(const float*)d_in[26];
    const float *wt2=(const float*)d_in[27], *bt2=(const float*)d_in[28];
    float* out = (float*)d_out;

    float *xg1f, *xg1b, *Y, *xg2f, *xg2b, *x64, *h2;
    cudaGetSymbolAddress((void**)&xg1f, g_xg1f);
    cudaGetSymbolAddress((void**)&xg1b, g_xg1b);
    cudaGetSymbolAddress((void**)&Y,    g_Y);
    cudaGetSymbolAddress((void**)&xg2f, g_xg2f);
    cudaGetSymbolAddress((void**)&xg2b, g_xg2b);
    cudaGetSymbolAddress((void**)&x64,  g_x64);
    cudaGetSymbolAddress((void**)&h2,   g_h2);

    static bool attr_done = false;
    if (!attr_done) {
        cudaFuncSetAttribute(lstm1_kernel, cudaFuncAttributeMaxDynamicSharedMemorySize, 160*1024);
        cudaFuncSetAttribute(lstm2_kernel, cudaFuncAttributeMaxDynamicSharedMemorySize, 80*1024);
        cudaFuncSetAttribute(gemm_mma_kernel, cudaFuncAttributeMaxDynamicSharedMemorySize, 2*STAGE_BYTES);
        attr_done = true;
    }

    emb_mlp_kernel<<<256, 256>>>(inputA, emb, w1,b1, w2,b2, w3,b3, x64);

    const size_t gsm = 2*STAGE_BYTES;
    gemm_mma_kernel<<<dim3(1024,4), 256, gsm>>>(inputB, k1f, bb1f, xg1f, BT, 512, 128);
    gemm_mma_kernel<<<dim3(1024,4), 256, gsm>>>(inputB, k1b, bb1b, xg1b, BT, 512, 128);

    size_t sm1 = (256*132 + 2*8*128 + 8*256 + 8*64) * sizeof(float);
    lstm1_kernel<<<dim3(64,2), 256, sm1>>>(xg1f, xg1b, r1f, r1b, Y);

    gemm_mma_kernel<<<dim3(1024,2), 256, gsm>>>(Y, k2f, bb2f, xg2f, BT, 256, 256);
    gemm_mma_kernel<<<dim3(1024,2), 256, gsm>>>(Y, k2b, bb2b, xg2b, BT, 256, 256);

    size_t sm2 = (256*68 + 2*4*64 + 4*256 + 4*64) * sizeof(float);
    lstm2_kernel<<<dim3(64,2), 256, sm2>>>(xg2f, xg2b, r2f, r2b, h2);

    head_kernel<<<1, 256>>>(x64, h2, wz1,bz1, wz2,bz2, wt1,bt1, wt2,bt2, out);
}

// round 5
// speedup vs baseline: 1.3980x; 1.0419x over previous
#include <cuda_runtime.h>
#include <cooperative_groups.h>
#include <cstdint>
namespace cg = cooperative_groups;

// ------------------------- scratch (device globals) -------------------------
#define BT (256*512)
__device__ float g_x64 [256*64];
__device__ float g_xB  [(size_t)BT*128];   // tf32-rounded copy of inputB
__device__ float g_xg1f[(size_t)BT*512];
__device__ float g_xg1b[(size_t)BT*512];
__device__ float g_Y   [(size_t)BT*256];   // lstm1 output, stored tf32-rounded
__device__ float g_xg2f[(size_t)BT*256];
__device__ float g_xg2b[(size_t)BT*256];
__device__ float g_h2  [256*128];
__device__ float g_wT  [4*65536];          // transposed+rounded weights [N,K]

// ------------------------- small PTX helpers --------------------------------
__device__ __forceinline__ uint32_t smem_u32(const void* p) {
    uint32_t a;
    asm("{ .reg .u64 t; cvta.to.shared.u64 t, %1; cvt.u32.u64 %0, t; }" : "=r"(a) : "l"(p));
    return a;
}
__device__ __forceinline__ uint32_t f2tf32(float v) {
    uint32_t r;
    asm("cvt.rna.tf32.f32 %0, %1;" : "=r"(r) : "f"(v));
    return r;
}
__device__ __forceinline__ void mma_tf32(float* c, const uint32_t* a, const uint32_t* b) {
    asm volatile("mma.sync.aligned.m16n8k8.row.col.f32.tf32.tf32.f32 "
        "{%0,%1,%2,%3},{%4,%5,%6,%7},{%8,%9},{%0,%1,%2,%3};"
        : "+f"(c[0]), "+f"(c[1]), "+f"(c[2]), "+f"(c[3])
        : "r"(a[0]), "r"(a[1]), "r"(a[2]), "r"(a[3]), "r"(b[0]), "r"(b[1]));
}
#define LDMATRIX_X4(r0, r1, r2, r3, addr) \
    asm volatile("ldmatrix.sync.aligned.m8n8.x4.shared.b16 {%0,%1,%2,%3}, [%4];" \
        : "=r"(r0), "=r"(r1), "=r"(r2), "=r"(r3) : "r"(addr))
#define CP_ASYNC16(dst, src) asm volatile("cp.async.cg.shared.global [%0], [%1], 16;" :: "r"(dst), "l"(src))
#define CP_COMMIT()          asm volatile("cp.async.commit_group;" ::: "memory")
#define CP_WAIT(n)           asm volatile("cp.async.wait_group %0;" :: "n"(n) : "memory")

// ------------------- prep: tf32 rounding / transpose+round ------------------
__global__ void __launch_bounds__(256)
round_kernel(const float* __restrict__ in, float* __restrict__ out, int n4)
{
    int i = blockIdx.x * 256 + threadIdx.x;
    if (i < n4) {
        float4 v = ((const float4*)in)[i];
        v.x = __uint_as_float(f2tf32(v.x));
        v.y = __uint_as_float(f2tf32(v.y));
        v.z = __uint_as_float(f2tf32(v.z));
        v.w = __uint_as_float(f2tf32(v.w));
        ((float4*)out)[i] = v;
    }
}
__global__ void __launch_bounds__(256)
transpose_round_kernel(const float* __restrict__ in, float* __restrict__ out, int K, int N)
{
    int idx = blockIdx.x * 256 + threadIdx.x;
    if (idx < K * N) {
        int n = idx / K, k = idx - n * K;
        out[idx] = __uint_as_float(f2tf32(in[k * N + n]));
    }
}

// ---- tf32 mma GEMM + bias: C[M,N] = A[M,K] @ Wt[N,K]^T + b  (pre-rounded) ---
// Block 128x128, BK=32, 2-stage cp.async, 8 warps (2m x 4n), warp tile 64x32.
// Both tiles in smem as [128 rows][36 floats]; ldmatrix fragment loads.
#define STAGE_BYTES 36864
__global__ void __launch_bounds__(256, 2)
gemm_mma_kernel(const float* __restrict__ A, const float* __restrict__ Wt,
                const float* __restrict__ bias, float* __restrict__ C,
                int M, int N, int K)
{
    extern __shared__ char smem[];
    const uint32_t smem_base = smem_u32(smem);
    const int tid = threadIdx.x;
    const int lane = tid & 31, wid = tid >> 5;
    const int m0 = blockIdx.x * 128, n0 = blockIdx.y * 128;
    const int wm = (wid >> 2) * 64, wn = (wid & 3) * 32;

    float acc[4][4][4];
    #pragma unroll
    for (int mt = 0; mt < 4; ++mt)
        #pragma unroll
        for (int nt = 0; nt < 4; ++nt)
            #pragma unroll
            for (int q = 0; q < 4; ++q) acc[mt][nt][q] = 0.f;

    // ldmatrix per-thread address offsets (bytes, relative to stage base)
    const int rowsel = ((lane & 16) >> 1) + (lane & 7);   // 0..15
    const int colsel = ((lane >> 3) & 1) * 4;             // 0 or 4 floats
    uint32_t offA[4], offB[2];
    #pragma unroll
    for (int mt = 0; mt < 4; ++mt)
        offA[mt] = (uint32_t)(((wm + mt * 16 + rowsel) * 36 + colsel) * 4);
    #pragma unroll
    for (int p = 0; p < 2; ++p)
        offB[p] = 18432u + (uint32_t)(((wn + p * 16 + rowsel) * 36 + colsel) * 4);

    const int nch = K >> 5;
    auto issue = [&](int ch, int stage) {
        const int kc = ch << 5;
        const uint32_t sA = smem_base + stage * STAGE_BYTES;
        const uint32_t sB = sA + 18432u;
        #pragma unroll
        for (int i = 0; i < 4; ++i) {          // A: 128 rows x 8 float4
            int idx = tid + i * 256;
            int row = idx >> 3, c4 = idx & 7;
            CP_ASYNC16(sA + row * 144 + c4 * 16,
                       A + (size_t)(m0 + row) * K + kc + c4 * 4);
        }
        #pragma unroll
        for (int i = 0; i < 4; ++i) {          // B: 128 n-rows x 8 float4
            int idx = tid + i * 256;
            int row = idx >> 3, c4 = idx & 7;
            CP_ASYNC16(sB + row * 144 + c4 * 16,
                       Wt + (size_t)(n0 + row) * K + kc + c4 * 4);
        }
        CP_COMMIT();
    };

    issue(0, 0);
    for (int ch = 0; ch < nch; ++ch) {
        if (ch + 1 < nch) { issue(ch + 1, (ch + 1) & 1); CP_WAIT(1); }
        else             { CP_WAIT(0); }
        __syncthreads();

        const uint32_t stg = smem_base + (ch & 1) * STAGE_BYTES;
        #pragma unroll
        for (int k8 = 0; k8 < 4; ++k8) {
            const uint32_t kb = (uint32_t)(k8 * 8 * 4);
            uint32_t a[4][4], b[4][2];
            #pragma unroll
            for (int mt = 0; mt < 4; ++mt)
                LDMATRIX_X4(a[mt][0], a[mt][2], a[mt][1], a[mt][3], stg + offA[mt] + kb);
            #pragma unroll
            for (int p = 0; p < 2; ++p)
                LDMATRIX_X4(b[2*p][0], b[2*p][1], b[2*p+1][0], b[2*p+1][1], stg + offB[p] + kb);
            #pragma unroll
            for (int mt = 0; mt < 4; ++mt)
                #pragma unroll
                for (int nt = 0; nt < 4; ++nt)
                    mma_tf32(acc[mt][nt], a[mt], b[nt]);
        }
        __syncthreads();
    }

    // --- epilogue: add bias, store ---
    #pragma unroll
    for (int mt = 0; mt < 4; ++mt) {
        int r = m0 + wm + mt * 16 + (lane >> 2);
        #pragma unroll
        for (int nt = 0; nt < 4; ++nt) {
            int col = n0 + wn + nt * 8 + (lane & 3) * 2;
            float b0 = __ldg(bias + col), b1 = __ldg(bias + col + 1);
            float2 v0 = make_float2(acc[mt][nt][0] + b0, acc[mt][nt][1] + b1);
            float2 v1 = make_float2(acc[mt][nt][2] + b0, acc[mt][nt][3] + b1);
            *(float2*)(C + (size_t)r * N + col)       = v0;
            *(float2*)(C + (size_t)(r + 8) * N + col) = v1;
        }
    }
}

// ------------------------- embedding MLP branch -----------------------------
__global__ void __launch_bounds__(256)
emb_mlp_kernel(const int* __restrict__ inputA, const float* __restrict__ emb,
               const float* __restrict__ w1, const float* __restrict__ b1,
               const float* __restrict__ w2, const float* __restrict__ b2,
               const float* __restrict__ w3, const float* __restrict__ b3,
               float* __restrict__ xout)
{
    __shared__ float x0[600], x1[256], x2[128];
    const int b = blockIdx.x, tid = threadIdx.x;
    for (int i = tid; i < 600; i += 256) {
        int la = i / 3, comp = i - la * 3;
        x0[i] = emb[inputA[b*200 + la]*3 + comp];
    }
    __syncthreads();
    {
        float acc = b1[tid];
        #pragma unroll 4
        for (int k = 0; k < 600; ++k) acc += x0[k] * w1[k*256 + tid];
        x1[tid] = fmaxf(acc, 0.f);
    }
    __syncthreads();
    if (tid < 128) {
        float acc = b2[tid];
        #pragma unroll 4
        for (int k = 0; k < 256; ++k) acc += x1[k] * w2[k*128 + tid];
        x2[tid] = fmaxf(acc, 0.f);
    }
    __syncthreads();
    if (tid < 64) {
        float acc = b3[tid];
        #pragma unroll 4
        for (int k = 0; k < 128; ++k) acc += x2[k] * w3[k*64 + tid];
        xout[b*64 + tid] = fmaxf(acc, 0.f);
    }
}

// -------------------- LSTM layer 1 (H=128), 2-CTA cluster -------------------
__global__ void __cluster_dims__(2,1,1) __launch_bounds__(256, 1)
lstm1_kernel(const float* __restrict__ xg1f, const float* __restrict__ xg1b,
             const float* __restrict__ r1f,  const float* __restrict__ r1b,
             float* __restrict__ Y)
{
    extern __shared__ float sm[];
    float* ws   = sm;                    // 256*132
    float* hbuf = sm + 256*132;          // 2*8*128
    float* gbuf = hbuf + 2*8*128;        // 8*256
    float* cst  = gbuf + 8*256;          // 8*64

    cg::cluster_group cl = cg::this_cluster();
    const int rank = cl.block_rank();
    const int dir  = blockIdx.y;
    const int b0   = (blockIdx.x >> 1) * 8;
    const int tid  = threadIdx.x;
    const float* xg = dir ? xg1b : xg1f;
    const float* Wr = dir ? r1b : r1f;

    for (int it = 0; it < 128; ++it) {
        int idx = tid + it*256;
        int c = idx & 255, k = idx >> 8;
        int gcol = ((c >> 6) << 7) + (rank << 6) + (c & 63);
        ws[c*132 + k] = Wr[k*512 + gcol];
    }
    for (int i = tid; i < 8*128; i += 256) hbuf[i] = 0.f;
    for (int i = tid; i < 8*64;  i += 256) cst[i]  = 0.f;

    float* peer_h = cl.map_shared_rank(hbuf, rank ^ 1);
    cl.sync();

    const int bg = tid >> 7;
    const int cp = tid & 127;
    const bool relu1 = (cp < 64);
    const int j  = cp & 63;
    const int gc0 = ((cp >> 6) << 7) + (rank << 6) + j;
    const int gc1 = (((cp >> 6) + 2) << 7) + (rank << 6) + j;
    const float4* w0p = (const float4*)(ws + cp*132);
    const float4* w1p = (const float4*)(ws + (cp + 128)*132);

    for (int t = 0; t < 512; ++t) {
        const int tt  = dir ? (511 - t) : t;
        const int cur = t & 1, nxt = cur ^ 1;

        float xv0[4], xv1[4];
        #pragma unroll
        for (int i = 0; i < 4; ++i) {
            size_t base = ((size_t)(b0 + (bg<<2) + i) * 512 + tt) * 512;
            xv0[i] = xg[base + gc0];
            xv1[i] = xg[base + gc1];
        }

        float a0[4] = {0.f,0.f,0.f,0.f}, a1[4] = {0.f,0.f,0.f,0.f};
        const float4* hp = (const float4*)(hbuf + cur*1024 + (bg<<2)*128);
        #pragma unroll 4
        for (int q = 0; q < 32; ++q) {
            float4 w0 = w0p[q], w1 = w1p[q];
            #pragma unroll
            for (int i = 0; i < 4; ++i) {
                float4 h4 = hp[i*32 + q];
                a0[i] += h4.x*w0.x + h4.y*w0.y + h4.z*w0.z + h4.w*w0.w;
                a1[i] += h4.x*w1.x + h4.y*w1.y + h4.z*w1.z + h4.w*w1.w;
            }
        }
        #pragma unroll
        for (int i = 0; i < 4; ++i) {
            float g0 = a0[i] + xv0[i];
            float g1 = a1[i] + xv1[i];
            g0 = 1.f / (1.f + __expf(-g0));
            g1 = relu1 ? fmaxf(g1, 0.f) : 1.f / (1.f + __expf(-g1));
            int bb = (bg << 2) + i;
            gbuf[bb*256 + cp]       = g0;
            gbuf[bb*256 + 128 + cp] = g1;
        }
        __syncthreads();

        #pragma unroll
        for (int s = tid; s < 512; s += 256) {
            int b = s >> 6, jj = s & 63;
            float iv = gbuf[b*256 + jj];
            float fv = gbuf[b*256 + 64 + jj];
            float cc = gbuf[b*256 + 128 + jj];
            float ov = gbuf[b*256 + 192 + jj];
            float cv = fv * cst[s] + iv * cc;
            cst[s] = cv;
            float hv = ov * fmaxf(cv, 0.f);
            int jg = (rank << 6) + jj;
            hbuf[nxt*1024 + b*128 + jg]  = hv;
            peer_h[nxt*1024 + b*128 + jg] = hv;
            // store tf32-rounded for the ldmatrix layer-2 GEMM
            Y[((size_t)(b0 + b) * 512 + tt) * 256 + dir*128 + jg] =
                __uint_as_float(f2tf32(hv));
        }
        cl.sync();
    }
}

// ------------------------- LSTM layer 2 (H=64) ------------------------------
__global__ void __launch_bounds__(256, 1)
lstm2_kernel(const float* __restrict__ xg2f, const float* __restrict__ xg2b,
             const float* __restrict__ r2f,  const float* __restrict__ r2b,
             float* __restrict__ hout)
{
    extern __shared__ float sm[];
    float* ws   = sm;                // 256*68
    float* hbuf = sm + 256*68;       // 2*4*64
    float* gbuf = hbuf + 2*4*64;     // 4*256
    float* cst  = gbuf + 4*256;      // 4*64

    const int dir = blockIdx.y;
    const int b0  = blockIdx.x * 4;
    const int tid = threadIdx.x;
    const float* xg = dir ? xg2b : xg2f;
    const float* Wr = dir ? r2b : r2f;

    for (int it = 0; it < 64; ++it) {
        int idx = tid + it*256;
        int c = idx & 255, k = idx >> 8;
        ws[c*68 + k] = Wr[k*256 + c];
    }
    for (int i = tid; i < 4*64*2; i += 256) hbuf[i] = 0.f;
    cst[tid] = 0.f;
    __syncthreads();

    const int c = tid;
    const int gate = c >> 6;
    const float4* wp = (const float4*)(ws + c*68);

    for (int t = 0; t < 512; ++t) {
        const int tt  = dir ? (511 - t) : t;
        const int cur = t & 1, nxt = cur ^ 1;

        float xv[4];
        #pragma unroll
        for (int i = 0; i < 4; ++i)
            xv[i] = xg[((size_t)(b0 + i) * 512 + tt) * 256 + c];

        float a[4] = {0.f,0.f,0.f,0.f};
        const float4* hp = (const float4*)(hbuf + cur*256);
        #pragma unroll 4
        for (int q = 0; q < 16; ++q) {
            float4 w4 = wp[q];
            #pragma unroll
            for (int i = 0; i < 4; ++i) {
                float4 h4 = hp[i*16 + q];
                a[i] += h4.x*w4.x + h4.y*w4.y + h4.z*w4.z + h4.w*w4.w;
            }
        }
        #pragma unroll
        for (int i = 0; i < 4; ++i) {
            float g = a[i] + xv[i];
            g = (gate == 2) ? fmaxf(g, 0.f) : 1.f / (1.f + __expf(-g));
            gbuf[i*256 + c] = g;
        }
        __syncthreads();

        {
            int b = tid >> 6, jj = tid & 63;
            float iv = gbuf[b*256 + jj];
            float fv = gbuf[b*256 + 64 + jj];
            float cc = gbuf[b*256 + 128 + jj];
            float ov = gbuf[b*256 + 192 + jj];
            float cv = fv * cst[tid] + iv * cc;
            cst[tid] = cv;
            hbuf[nxt*256 + b*64 + jj] = ov * fmaxf(cv, 0.f);
        }
        __syncthreads();
    }
    {
        int b = tid >> 6, jj = tid & 63;
        hout[(size_t)(b0 + b) * 128 + dir*64 + jj] = hbuf[0*256 + b*64 + jj];
    }
}

// ------------------------------ heads ---------------------------------------
__global__ void __launch_bounds__(256)
head_kernel(const float* __restrict__ x64, const float* __restrict__ h2,
            const float* __restrict__ wz1, const float* __restrict__ bz1,
            const float* __restrict__ wz2, const float* __restrict__ bz2,
            const float* __restrict__ wt1, const float* __restrict__ bt1,
            const float* __restrict__ wt2, const float* __restrict__ bt2,
            float* __restrict__ out)
{
    const int b = threadIdx.x;
    float comb[192];
    #pragma unroll 4
    for (int k = 0; k < 64; ++k)  comb[k]      = x64[b*64 + k];
    #pragma unroll 4
    for (int k = 0; k < 128; ++k) comb[64 + k] = h2[b*128 + k];

    float z0 = bz1[0], z1 = bz1[1], t0 = bt1[0], t1 = bt1[1];
    #pragma unroll 4
    for (int k = 0; k < 192; ++k) {
        float v = comb[k];
        z0 += v * wz1[k*2 + 0]; z1 += v * wz1[k*2 + 1];
        t0 += v * wt1[k*2 + 0]; t1 += v * wt1[k*2 + 1];
    }
    out[b]       = fmaxf(z0,0.f)*wz2[0] + fmaxf(z1,0.f)*wz2[1] + bz2[0];
    out[256 + b] = fmaxf(t0,0.f)*wt2[0] + fmaxf(t1,0.f)*wt2[1] + bt2[0];
}

// ------------------------------ launcher ------------------------------------
extern "C" void kernel_launch(void* const* d_in, const int* in_sizes, int n_in,
                              void* d_out, int out_size)
{
    const int*   inputA = (const int*)  d_in[0];
    const float* inputB = (const float*)d_in[1];
    const float* emb = (const float*)d_in[2];
    const float *w1=(const float*)d_in[3],  *b1=(const float*)d_in[4];
    const float *w2=(const float*)d_in[5],  *b2=(const float*)d_in[6];
    const float *w3=(const float*)d_in[7],  *b3=(const float*)d_in[8];
    const float *k1f=(const float*)d_in[9],  *r1f=(const float*)d_in[10], *bb1f=(const float*)d_in[11];
    const float *k1b=(const float*)d_in[12], *r1b=(const float*)d_in[13], *bb1b=(const float*)d_in[14];
    const float *k2f=(const float*)d_in[15], *r2f=(const float*)d_in[16], *bb2f=(const float*)d_in[17];
    const float *k2b=(const float*)d_in[18], *r2b=(const float*)d_in[19], *bb2b=(const float*)d_in[20];
    const float *wz1=(const float*)d_in[21], *bz1=(const float*)d_in[22];
    const float *wz2=(const float*)d_in[23], *bz2=(const float*)d_in[24];
    const float *wt1=(const float*)d_in[25], *bt1=(const float*)d_in[26];
    const float *wt2=(const float*)d_in[27], *bt2=(const float*)d_in[28];
    float* out = (float*)d_out;

    float *xB, *xg1f, *xg1b, *Y, *xg2f, *xg2b, *x64, *h2, *wT;
    cudaGetSymbolAddress((void**)&xB,   g_xB);
    cudaGetSymbolAddress((void**)&xg1f, g_xg1f);
    cudaGetSymbolAddress((void**)&xg1b, g_xg1b);
    cudaGetSymbolAddress((void**)&Y,    g_Y);
    cudaGetSymbolAddress((void**)&xg2f, g_xg2f);
    cudaGetSymbolAddress((void**)&xg2b, g_xg2b);
    cudaGetSymbolAddress((void**)&x64,  g_x64);
    cudaGetSymbolAddress((void**)&h2,   g_h2);
    cudaGetSymbolAddress((void**)&wT,   g_wT);
    float* wt1f = wT;
    float* wt1b = wT + 65536;
    float* wt2f = wT + 2*65536;
    float* wt2b = wT + 3*65536;

    static bool attr_done = false;
    if (!attr_done) {
        cudaFuncSetAttribute(lstm1_kernel, cudaFuncAttributeMaxDynamicSharedMemorySize, 160*1024);
        cudaFuncSetAttribute(lstm2_kernel, cudaFuncAttributeMaxDynamicSharedMemorySize, 80*1024);
        cudaFuncSetAttribute(gemm_mma_kernel, cudaFuncAttributeMaxDynamicSharedMemorySize, 2*STAGE_BYTES);
        attr_done = true;
    }

    // prep: tf32-round A, transpose+round weights
    round_kernel<<<(BT*128/4 + 255)/256, 256>>>(inputB, xB, BT*128/4);
    transpose_round_kernel<<<(65536+255)/256, 256>>>(k1f, wt1f, 128, 512);
    transpose_round_kernel<<<(65536+255)/256, 256>>>(k1b, wt1b, 128, 512);
    transpose_round_kernel<<<(65536+255)/256, 256>>>(k2f, wt2f, 256, 256);
    transpose_round_kernel<<<(65536+255)/256, 256>>>(k2b, wt2b, 256, 256);

    emb_mlp_kernel<<<256, 256>>>(inputA, emb, w1,b1, w2,b2, w3,b3, x64);

    const size_t gsm = 2*STAGE_BYTES;
    gemm_mma_kernel<<<dim3(1024,4), 256, gsm>>>(xB, wt1f, bb1f, xg1f, BT, 512, 128);
    gemm_mma_kernel<<<dim3(1024,4), 256, gsm>>>(xB, wt1b, bb1b, xg1b, BT, 512, 128);

    size_t sm1 = (256*132 + 2*8*128 + 8*256 + 8*64) * sizeof(float);
    lstm1_kernel<<<dim3(64,2), 256, sm1>>>(xg1f, xg1b, r1f, r1b, Y);

    gemm_mma_kernel<<<dim3(1024,2), 256, gsm>>>(Y, wt2f, bb2f, xg2f, BT, 256, 256);
    gemm_mma_kernel<<<dim3(1024,2), 256, gsm>>>(Y, wt2b, bb2b, xg2b, BT, 256, 256);

    size_t sm2 = (256*68 + 2*4*64 + 4*256 + 4*64) * sizeof(float);
    lstm2_kernel<<<dim3(64,2), 256, sm2>>>(xg2f, xg2b, r2f, r2b, h2);

    head_kernel<<<1, 256>>>(x64, h2, wz1,bz1, wz2,bz2, wt1,bt1, wt2,bt2, out);
}